// round 15
// baseline (speedup 1.0000x reference)
#include <cuda_runtime.h>
#include <cuda_bf16.h>
#include <cuda_fp16.h>
#include <cstdint>

#define B_ 2
#define QL_ 2048
#define KVL_ 2048
#define DM_ 1024
#define NH_ 16
#define DQK_ 64
#define LOG2E 1.4426950408889634f

typedef unsigned long long u64;

// ---- warp-level MMA helpers (base-arch PTX: works at compute_103) ----
__device__ __forceinline__ uint32_t smem_u32(const void* p) {
    uint32_t a;
    asm("{ .reg .u64 t; cvta.to.shared.u64 t, %1; cvt.u32.u64 %0, t; }" : "=r"(a) : "l"(p));
    return a;
}
__device__ __forceinline__ void ldsm4(uint32_t &r0, uint32_t &r1, uint32_t &r2, uint32_t &r3,
                                      uint32_t addr) {
    asm volatile("ldmatrix.sync.aligned.m8n8.x4.shared.b16 {%0,%1,%2,%3}, [%4];"
                 : "=r"(r0), "=r"(r1), "=r"(r2), "=r"(r3) : "r"(addr));
}
__device__ __forceinline__ void ldsm4t(uint32_t &r0, uint32_t &r1, uint32_t &r2, uint32_t &r3,
                                       uint32_t addr) {
    asm volatile("ldmatrix.sync.aligned.m8n8.x4.trans.shared.b16 {%0,%1,%2,%3}, [%4];"
                 : "=r"(r0), "=r"(r1), "=r"(r2), "=r"(r3) : "r"(addr));
}
__device__ __forceinline__ void mma16816(float* d, const uint32_t* a, uint32_t b0, uint32_t b1) {
    asm volatile(
        "mma.sync.aligned.m16n8k16.row.col.f32.bf16.bf16.f32 "
        "{%0,%1,%2,%3}, {%4,%5,%6,%7}, {%8,%9}, {%0,%1,%2,%3};"
        : "+f"(d[0]), "+f"(d[1]), "+f"(d[2]), "+f"(d[3])
        : "r"(a[0]), "r"(a[1]), "r"(a[2]), "r"(a[3]), "r"(b0), "r"(b1));
}
__device__ __forceinline__ void mma16816h(float* d, const uint32_t* a, uint32_t b0, uint32_t b1) {
    asm volatile(
        "mma.sync.aligned.m16n8k16.row.col.f32.f16.f16.f32 "
        "{%0,%1,%2,%3}, {%4,%5,%6,%7}, {%8,%9}, {%0,%1,%2,%3};"
        : "+f"(d[0]), "+f"(d[1]), "+f"(d[2]), "+f"(d[3])
        : "r"(a[0]), "r"(a[1]), "r"(a[2]), "r"(a[3]), "r"(b0), "r"(b1));
}
__device__ __forceinline__ uint32_t packh(float lo, float hi) {
    uint32_t d;
    asm("cvt.rn.f16x2.f32 %0, %1, %2;" : "=r"(d) : "f"(hi), "f"(lo));
    return d;
}
__device__ __forceinline__ void cpa16(uint32_t dst, const void* src) {
    asm volatile("cp.async.cg.shared.global [%0], [%1], 16;" :: "r"(dst), "l"(src));
}
#define CP_COMMIT() asm volatile("cp.async.commit_group;" ::: "memory")
#define CP_WAIT1()  asm volatile("cp.async.wait_group 1;" ::: "memory")

// ---- packed f32x2 helpers ----
__device__ __forceinline__ u64 ffma2_(u64 a, u64 b, u64 c) {
    u64 d; asm("fma.rn.f32x2 %0, %1, %2, %3;" : "=l"(d) : "l"(a), "l"(b), "l"(c)); return d;
}
__device__ __forceinline__ u64 fmul2_(u64 a, u64 b) {
    u64 d; asm("mul.rn.f32x2 %0, %1, %2;" : "=l"(d) : "l"(a), "l"(b)); return d;
}
__device__ __forceinline__ u64 fadd2_(u64 a, u64 b) {
    u64 d; asm("add.rn.f32x2 %0, %1, %2;" : "=l"(d) : "l"(a), "l"(b)); return d;
}
__device__ __forceinline__ u64 dup2_(float x) {
    u64 r; asm("mov.b64 %0, {%1, %1};" : "=l"(r) : "f"(x)); return r;
}
__device__ __forceinline__ u64 pack2_(float lo, float hi) {
    u64 r; asm("mov.b64 %0, {%1, %2};" : "=l"(r) : "f"(lo), "f"(hi)); return r;
}
__device__ __forceinline__ u64 packu2_(uint32_t lo, uint32_t hi) {
    u64 r; asm("mov.b64 %0, {%1, %2};" : "=l"(r) : "r"(lo), "r"(hi)); return r;
}
__device__ __forceinline__ void unpack2_(u64 v, float &lo, float &hi) {
    asm("mov.b64 {%0, %1}, %2;" : "=f"(lo), "=f"(hi) : "l"(v));
}
__device__ __forceinline__ void unpack2u_(u64 v, uint32_t &lo, uint32_t &hi) {
    asm("mov.b64 {%0, %1}, %2;" : "=r"(lo), "=r"(hi) : "l"(v));
}

// scalar 2^x (x <= 0, clamped). FMA pipe only.
__device__ __forceinline__ float exp2s_(float x) {
    x = fmaxf(x, -120.f);
    float y = x + 12582912.0f;
    int zi = __float_as_int(y);
    float f = x - (y - 12582912.0f);
    float p = fmaf(f, 0.0555041086648216f, 0.2402265069591007f);
    p = fmaf(f, p, 0.6931471805599453f);
    p = fmaf(f, p, 1.0f);
    return p * __int_as_float((zi - 4194177) << 23);
}
// packed 2^x on two floats at once (FFMA2 pipe)
__device__ __forceinline__ u64 fexp2_2(float a, float b) {
    a = fmaxf(a, -120.f);
    b = fmaxf(b, -120.f);
    u64 x = pack2_(a, b);
    u64 y = fadd2_(x, dup2_(12582912.0f));
    uint32_t zlo, zhi;
    unpack2u_(y, zlo, zhi);
    u64 i_f = fadd2_(y, dup2_(-12582912.0f));
    u64 f = ffma2_(i_f, dup2_(-1.0f), x);
    u64 p = ffma2_(f, dup2_(0.0555041086648216f), dup2_(0.2402265069591007f));
    p = ffma2_(f, p, dup2_(0.6931471805599453f));
    p = ffma2_(f, p, dup2_(1.0f));
    uint32_t slo = (zlo - 4194177u) << 23;
    uint32_t shi = (zhi - 4194177u) << 23;
    return fmul2_(p, packu2_(slo, shi));
}

// ---- scratch (device globals: allocation-free rule) ----
__device__ __align__(16) __nv_bfloat16 g_nh[B_*QL_*DM_],    g_nl[B_*QL_*DM_];
__device__ __align__(16) __nv_bfloat16 g_kvh_h[B_*KVL_*DM_], g_kvh_l[B_*KVL_*DM_];
__device__ __align__(16) __nv_bfloat16 g_wqh[DM_*DM_],       g_wql[DM_*DM_];
__device__ __align__(16) __nv_bfloat16 g_wkvh[2*DM_*DM_],    g_wkvl[2*DM_*DM_];
__device__ __align__(16) __nv_bfloat16 g_woh[DM_*DM_],       g_wol[DM_*DM_];
__device__ __align__(16) __half        g_qf[B_*NH_*QL_*DQK_];
__device__ __align__(16) __half        g_kf[B_*NH_*KVL_*DQK_];   // pre-scaled by LOG2E
__device__ __align__(16) __half        g_vf[B_*NH_*KVL_*DQK_];
__device__ __align__(16) __nv_bfloat16 g_aoh[B_*QL_*DM_],    g_aol[B_*QL_*DM_];

__device__ __forceinline__ void split_bf16(float v, __nv_bfloat16 &h, __nv_bfloat16 &l) {
    h = __float2bfloat16(v);
    l = __float2bfloat16(v - __bfloat162float(h));
}

// ---------------------------------------------------------------------------
// RMSNorm -> bf16 hi/lo
// ---------------------------------------------------------------------------
__global__ __launch_bounds__(256) void rmsnorm_kernel(const float* __restrict__ x,
                                                      const float* __restrict__ w) {
    int row = blockIdx.x;
    int t = threadIdx.x;
    float4 v = ((const float4*)(x + (size_t)row*DM_))[t];
    float ss = v.x*v.x + v.y*v.y + v.z*v.z + v.w*v.w;
    #pragma unroll
    for (int o = 16; o; o >>= 1) ss += __shfl_xor_sync(0xffffffffu, ss, o);
    __shared__ float sred[8];
    if ((t & 31) == 0) sred[t >> 5] = ss;
    __syncthreads();
    float tot = sred[0]+sred[1]+sred[2]+sred[3]+sred[4]+sred[5]+sred[6]+sred[7];
    float sc = rsqrtf(tot * (1.0f/DM_) + 1e-6f);
    float4 wv = ((const float4*)w)[t];
    float o4[4] = {v.x*sc*wv.x, v.y*sc*wv.y, v.z*sc*wv.z, v.w*sc*wv.w};
    __nv_bfloat16 h[4], l[4];
    #pragma unroll
    for (int i = 0; i < 4; i++) split_bf16(o4[i], h[i], l[i]);
    size_t base = (size_t)row*DM_ + t*4;
    *(__nv_bfloat162*)(g_nh + base)     = __nv_bfloat162(h[0], h[1]);
    *(__nv_bfloat162*)(g_nh + base + 2) = __nv_bfloat162(h[2], h[3]);
    *(__nv_bfloat162*)(g_nl + base)     = __nv_bfloat162(l[0], l[1]);
    *(__nv_bfloat162*)(g_nl + base + 2) = __nv_bfloat162(l[2], l[3]);
}

// ---------------------------------------------------------------------------
// Elementwise fp32 -> bf16 hi/lo
// ---------------------------------------------------------------------------
__global__ __launch_bounds__(256) void split_kernel(const float* __restrict__ x,
                                                    __nv_bfloat16* __restrict__ oh,
                                                    __nv_bfloat16* __restrict__ ol) {
    size_t i = ((size_t)blockIdx.x*256 + threadIdx.x)*4;
    float4 v = *(const float4*)(x + i);
    float a[4] = {v.x, v.y, v.z, v.w};
    __nv_bfloat16 h[4], l[4];
    #pragma unroll
    for (int k = 0; k < 4; k++) split_bf16(a[k], h[k], l[k]);
    *(__nv_bfloat162*)(oh + i)     = __nv_bfloat162(h[0], h[1]);
    *(__nv_bfloat162*)(oh + i + 2) = __nv_bfloat162(h[2], h[3]);
    *(__nv_bfloat162*)(ol + i)     = __nv_bfloat162(l[0], l[1]);
    *(__nv_bfloat162*)(ol + i + 2) = __nv_bfloat162(l[2], l[3]);
}

// ---------------------------------------------------------------------------
// Merged weight transpose + split (3 weights in one launch, z-dispatch).
// ---------------------------------------------------------------------------
__global__ __launch_bounds__(256) void wconv_all(const float* __restrict__ wq,
                                                 const float* __restrict__ wkv,
                                                 const float* __restrict__ wo) {
    const int z = blockIdx.z;
    const float* w;
    __nv_bfloat16 *th, *tl;
    int N, nbase;
    if (z == 0)      { w = wq;  th = g_wqh;  tl = g_wql;  N = DM_;   nbase = 0; }
    else if (z == 3) { w = wo;  th = g_woh;  tl = g_wol;  N = DM_;   nbase = 0; }
    else             { w = wkv; th = g_wkvh; tl = g_wkvl; N = 2*DM_; nbase = (z-1)*DM_; }

    __shared__ float t[32][33];
    int tx = threadIdx.x & 31, ty = threadIdx.x >> 5;
    int n0 = nbase + blockIdx.x*32, k0 = blockIdx.y*32;
    #pragma unroll
    for (int i = 0; i < 4; i++)
        t[ty + i*8][tx] = w[(size_t)(k0 + ty + i*8)*N + n0 + tx];
    __syncthreads();
    #pragma unroll
    for (int i = 0; i < 4; i++) {
        int n = n0 + ty + i*8;
        float v = t[tx][ty + i*8];
        __nv_bfloat16 h, l;
        split_bf16(v, h, l);
        th[(size_t)n*DM_ + k0 + tx] = h;
        tl[(size_t)n*DM_ + k0 + tx] = l;
    }
}

// ---------------------------------------------------------------------------
// GEMM: 512 threads / 16 warps, tile 128x128, warp tile 16x64 (wm 0..7, wn 0..1).
// KC=32, KP=40, 2-stage cp.async (80KB, single CTA by design; 4 warps/SMSP).
// ---------------------------------------------------------------------------
#define KC 32
#define KP 40
#define NKT (DM_/KC)
#define GTILE (128*KP)
#define GSTAGE (4*GTILE*2)

#define GEMM_KS_STEP(uAh_, uAl_, uBh_, uBl_)                                   \
    do {                                                                        \
        uint32_t ah[4], al[4];                                                  \
        {                                                                       \
            uint32_t off = (arow*KP + ks*16 + akof)*2;                          \
            ldsm4(ah[0], ah[1], ah[2], ah[3], (uAh_) + off);                    \
            ldsm4(al[0], al[1], al[2], al[3], (uAl_) + off);                    \
        }                                                                       \
        _Pragma("unroll")                                                       \
        for (int nt4 = 0; nt4 < 4; nt4++) {                                     \
            uint32_t bh[4], bl[4];                                              \
            uint32_t off = ((brow + nt4*16)*KP + ks*16 + bkof)*2;               \
            ldsm4(bh[0], bh[1], bh[2], bh[3], (uBh_) + off);                    \
            ldsm4(bl[0], bl[1], bl[2], bl[3], (uBl_) + off);                    \
            _Pragma("unroll")                                                   \
            for (int s = 0; s < 2; s++)                                         \
                mma16816(acc[nt4*2 + s], ah, bh[2*s], bh[2*s+1]);               \
            _Pragma("unroll")                                                   \
            for (int s = 0; s < 2; s++)                                         \
                mma16816(acc[nt4*2 + s], ah, bl[2*s], bl[2*s+1]);               \
            _Pragma("unroll")                                                   \
            for (int s = 0; s < 2; s++)                                         \
                mma16816(acc[nt4*2 + s], al, bh[2*s], bh[2*s+1]);               \
        }                                                                       \
    } while (0)

// ---------------------------------------------------------------------------
// Merged Q + KV projection GEMM. Q, K -> plain fp16 (K scaled by LOG2E), V fp16.
// ---------------------------------------------------------------------------
__global__ __launch_bounds__(512, 1) void mma_gemm_qkv()
{
    extern __shared__ __align__(16) char smem[];
    const uint32_t uS = smem_u32(smem);

    const int tid = threadIdx.x, lane = tid & 31, w = tid >> 5;
    const int wm = w & 7, wn = w >> 3;
    const int nbr = blockIdx.x, mb = blockIdx.y;
    const bool isQ = nbr < 8;
    const int nb = isQ ? nbr : nbr - 8;

    const __nv_bfloat16* Ah = isQ ? g_nh : g_kvh_h;
    const __nv_bfloat16* Al = isQ ? g_nl : g_kvh_l;
    const __nv_bfloat16* Bh = isQ ? g_wqh : g_wkvh;
    const __nv_bfloat16* Bl = isQ ? g_wql : g_wkvl;

    float acc[8][4];
    #pragma unroll
    for (int j = 0; j < 8; j++)
        #pragma unroll
        for (int k = 0; k < 4; k++) acc[j][k] = 0.f;

    const __nv_bfloat16* srcs[4] = {
        Ah + (size_t)(mb*128)*DM_, Al + (size_t)(mb*128)*DM_,
        Bh + (size_t)(nb*128)*DM_, Bl + (size_t)(nb*128)*DM_
    };

    const int arow = wm*16 + (lane & 15);
    const int akof = (lane >> 4) << 3;
    const int brow = wn*64 + (lane & 7) + ((lane >> 4) << 3);
    const int bkof = ((lane >> 3) & 1) << 3;

    // 512 threads: one full tile per pass (128 rows x 4 chunks)
    const int lr = tid >> 2, lc = tid & 3;
    auto load_stage = [&](int s, int kt) {
        uint32_t base = uS + s*GSTAGE + (lr*KP + lc*8)*2;
        #pragma unroll
        for (int t = 0; t < 4; t++)
            cpa16(base + t*(GTILE*2), srcs[t] + kt*KC + (size_t)lr*DM_ + lc*8);
    };

    load_stage(0, 0); CP_COMMIT();
    load_stage(1, 1); CP_COMMIT();

    for (int kt = 0; kt < NKT; kt++) {
        CP_WAIT1();
        __syncthreads();
        const uint32_t sb = uS + (kt & 1)*GSTAGE;
        const uint32_t uAh = sb, uAl = sb + GTILE*2, uBh = sb + 2*GTILE*2, uBl = sb + 3*GTILE*2;

        #pragma unroll
        for (int ks = 0; ks < 2; ks++)
            GEMM_KS_STEP(uAh, uAl, uBh, uBl);

        __syncthreads();
        if (kt + 2 < NKT) load_stage(kt & 1, kt + 2);
        CP_COMMIT();
    }

    #pragma unroll
    for (int nt = 0; nt < 8; nt++) {
        #pragma unroll
        for (int hf = 0; hf < 2; hf++) {
            float v0 = acc[nt][hf*2], v1 = acc[nt][hf*2+1];
            int m = mb*128 + wm*16 + (lane >> 2) + hf*8;
            int n0 = nb*128 + wn*64 + nt*8 + (lane & 3)*2;
            if (isQ) {
                int b = m >> 11, q = m & 2047, hh = n0 >> 6, d = n0 & 63;
                size_t base = (((size_t)b*NH_ + hh)*QL_ + q)*DQK_ + d;
                *(__half2*)(g_qf + base) = __half2(__float2half(v0), __float2half(v1));
            } else {
                int b = m >> 11, kl = m & 2047;
                int sf = n0 >> 10, hh = (n0 >> 6) & 15, d = n0 & 63;
                size_t base = (((size_t)b*NH_ + hh)*KVL_ + kl)*DQK_ + d;
                if (sf == 0) {
                    *(__half2*)(g_kf + base) =
                        __half2(__float2half(v0*LOG2E), __float2half(v1*LOG2E));
                } else {
                    *(__half2*)(g_vf + base) = __half2(__float2half(v0), __float2half(v1));
                }
            }
        }
    }
}

// ---------------------------------------------------------------------------
// O projection + residual GEMM (bf16x3), 512 threads
// ---------------------------------------------------------------------------
__global__ __launch_bounds__(512, 1) void mma_gemm_o(
    const float* __restrict__ resid, float* __restrict__ Cout)
{
    extern __shared__ __align__(16) char smem[];
    const uint32_t uS = smem_u32(smem);

    const int tid = threadIdx.x, lane = tid & 31, w = tid >> 5;
    const int wm = w & 7, wn = w >> 3;
    const int nb = blockIdx.x, mb = blockIdx.y;

    float acc[8][4];
    #pragma unroll
    for (int j = 0; j < 8; j++)
        #pragma unroll
        for (int k = 0; k < 4; k++) acc[j][k] = 0.f;

    const __nv_bfloat16* srcs[4] = {
        g_aoh + (size_t)(mb*128)*DM_, g_aol + (size_t)(mb*128)*DM_,
        g_woh + (size_t)(nb*128)*DM_, g_wol + (size_t)(nb*128)*DM_
    };

    const int arow = wm*16 + (lane & 15);
    const int akof = (lane >> 4) << 3;
    const int brow = wn*64 + (lane & 7) + ((lane >> 4) << 3);
    const int bkof = ((lane >> 3) & 1) << 3;

    const int lr = tid >> 2, lc = tid & 3;
    auto load_stage = [&](int s, int kt) {
        uint32_t base = uS + s*GSTAGE + (lr*KP + lc*8)*2;
        #pragma unroll
        for (int t = 0; t < 4; t++)
            cpa16(base + t*(GTILE*2), srcs[t] + kt*KC + (size_t)lr*DM_ + lc*8);
    };

    load_stage(0, 0); CP_COMMIT();
    load_stage(1, 1); CP_COMMIT();

    for (int kt = 0; kt < NKT; kt++) {
        CP_WAIT1();
        __syncthreads();
        const uint32_t sb = uS + (kt & 1)*GSTAGE;
        const uint32_t uAh = sb, uAl = sb + GTILE*2, uBh = sb + 2*GTILE*2, uBl = sb + 3*GTILE*2;

        #pragma unroll
        for (int ks = 0; ks < 2; ks++)
            GEMM_KS_STEP(uAh, uAl, uBh, uBl);

        __syncthreads();
        if (kt + 2 < NKT) load_stage(kt & 1, kt + 2);
        CP_COMMIT();
    }

    #pragma unroll
    for (int nt = 0; nt < 8; nt++) {
        #pragma unroll
        for (int hf = 0; hf < 2; hf++) {
            float v0 = acc[nt][hf*2], v1 = acc[nt][hf*2+1];
            int m = mb*128 + wm*16 + (lane >> 2) + hf*8;
            int n0 = nb*128 + wn*64 + nt*8 + (lane & 3)*2;
            size_t idx = (size_t)m*DM_ + n0;
            Cout[idx]     = v0 + resid[idx];
            Cout[idx + 1] = v1 + resid[idx + 1];
        }
    }
}

// ---------------------------------------------------------------------------
// HMMA flash attention: S single-term fp16 (K pre-scaled LOG2E), PV fp16.
// 2-stage cp.async KV pipeline. (unchanged from R13 best)
// ---------------------------------------------------------------------------
#define FQBYTES (128*72*2)
#define FKTILE  (64*72*2)
#define FSTAGE  (2*FKTILE)
__global__ __launch_bounds__(128, 3) void flash_kernel()
{
    extern __shared__ __align__(16) char fsm[];
    const uint32_t uS = smem_u32(fsm);
    const uint32_t uQf = uS;

    const int tid = threadIdx.x, lane = tid & 31, w = tid >> 5;
    const int qb = blockIdx.x, h = blockIdx.y, b = blockIdx.z;
    const size_t qoff = (((size_t)b*NH_ + h)*QL_ + qb*128)*DQK_;
    const size_t koff = (((size_t)b*NH_ + h)*KVL_)*DQK_;

    #pragma unroll
    for (int i = 0; i < 8; i++) {
        int id = tid + i*128, r = id >> 3, c = id & 7;
        *(uint4*)(fsm + (r*72 + c*8)*2) = *(const uint4*)(g_qf + qoff + (size_t)r*DQK_ + c*8);
    }

    const char* gsrc[2] = {(const char*)(g_kf + koff), (const char*)(g_vf + koff)};
    auto load_kv = [&](int s, int jt) {
        uint32_t base = uS + FQBYTES + s*FSTAGE;
        #pragma unroll
        for (int i = 0; i < 8; i++) {
            int id = tid + i*128;
            int t = id >> 9, cid = id & 511;
            int r = cid >> 3, c = cid & 7;
            uint32_t dst = base + t*FKTILE + (r*72 + c*8)*2;
            cpa16(dst, gsrc[t] + ((size_t)(jt*64 + r)*DQK_ + c*8)*2);
        }
    };

    const int arow = w*32 + (lane & 15);
    const int akof = (lane >> 4) << 3;
    const int krow = (lane & 7) + ((lane >> 4) << 3);
    const int kkof = ((lane >> 3) & 1) << 3;
    const int vrow = (lane & 7) + (((lane >> 3) & 1) << 3);
    const int vcol = (lane >> 4) << 3;

    float m_[2][2], l_[2][2], oacc[2][8][4];
    #pragma unroll
    for (int mt = 0; mt < 2; mt++)
        #pragma unroll
        for (int hf = 0; hf < 2; hf++) { m_[mt][hf] = -1e30f; l_[mt][hf] = 0.f; }
    #pragma unroll
    for (int mt = 0; mt < 2; mt++)
        #pragma unroll
        for (int nt = 0; nt < 8; nt++)
            #pragma unroll
            for (int e = 0; e < 4; e++) oacc[mt][nt][e] = 0.f;

    load_kv(0, 0); CP_COMMIT();
    load_kv(1, 1); CP_COMMIT();

    const int NJT = KVL_/64;
    for (int jt = 0; jt < NJT; jt++) {
        CP_WAIT1();
        __syncthreads();
        const uint32_t sb = uS + FQBYTES + (jt & 1)*FSTAGE;
        const uint32_t uKf = sb, uVf = sb + FKTILE;

        float sacc[2][8][4];
        #pragma unroll
        for (int mt = 0; mt < 2; mt++)
            #pragma unroll
            for (int nt = 0; nt < 8; nt++)
                #pragma unroll
                for (int e = 0; e < 4; e++) sacc[mt][nt][e] = 0.f;

        #pragma unroll
        for (int ks = 0; ks < 4; ks++) {
            uint32_t aq[2][4];
            #pragma unroll
            for (int mt = 0; mt < 2; mt++) {
                uint32_t off = ((arow + mt*16)*72 + ks*16 + akof)*2;
                ldsm4(aq[mt][0], aq[mt][1], aq[mt][2], aq[mt][3], uQf + off);
            }
            #pragma unroll
            for (int nn = 0; nn < 4; nn++) {
                uint32_t bk[4];
                uint32_t off = ((krow + nn*16)*72 + ks*16 + kkof)*2;
                ldsm4(bk[0], bk[1], bk[2], bk[3], uKf + off);
                #pragma unroll
                for (int mt = 0; mt < 2; mt++)
                    #pragma unroll
                    for (int s = 0; s < 2; s++)
                        mma16816h(sacc[mt][nn*2 + s], aq[mt], bk[2*s], bk[2*s+1]);
            }
        }

        // softmax: lazy rescale + packed exp2
        u64 pexp[2][8][2];
        #pragma unroll
        for (int mt = 0; mt < 2; mt++) {
            #pragma unroll
            for (int hf = 0; hf < 2; hf++) {
                float tmax = -1e30f;
                #pragma unroll
                for (int nt = 0; nt < 8; nt++)
                    tmax = fmaxf(tmax, fmaxf(sacc[mt][nt][hf*2], sacc[mt][nt][hf*2+1]));
                tmax = fmaxf(tmax, __shfl_xor_sync(0xffffffffu, tmax, 1));
                tmax = fmaxf(tmax, __shfl_xor_sync(0xffffffffu, tmax, 2));
                bool need = tmax > m_[mt][hf];
                if (__ballot_sync(0xffffffffu, need)) {
                    float nm = fmaxf(m_[mt][hf], tmax);
                    float corr = exp2s_(m_[mt][hf] - nm);
                    m_[mt][hf] = nm;
                    l_[mt][hf] *= corr;
                    #pragma unroll
                    for (int nt = 0; nt < 8; nt++) {
                        oacc[mt][nt][hf*2]   *= corr;
                        oacc[mt][nt][hf*2+1] *= corr;
                    }
                }
                float mr = m_[mt][hf];
                u64 rs2 = 0ull;
                #pragma unroll
                for (int nt = 0; nt < 8; nt++) {
                    u64 pe = fexp2_2(sacc[mt][nt][hf*2] - mr, sacc[mt][nt][hf*2+1] - mr);
                    pexp[mt][nt][hf] = pe;
                    rs2 = fadd2_(rs2, pe);
                }
                float rlo, rhi;
                unpack2_(rs2, rlo, rhi);
                float rs = rlo + rhi;
                rs += __shfl_xor_sync(0xffffffffu, rs, 1);
                rs += __shfl_xor_sync(0xffffffffu, rs, 2);
                l_[mt][hf] += rs;
            }
        }

        // O += P V
        #pragma unroll
        for (int kk = 0; kk < 4; kk++) {
            uint32_t aP[2][4];
            #pragma unroll
            for (int mt = 0; mt < 2; mt++) {
                #pragma unroll
                for (int q = 0; q < 4; q++) {
                    float p0, p1;
                    unpack2_(pexp[mt][2*kk + (q >> 1)][q & 1], p0, p1);
                    aP[mt][q] = packh(p0, p1);
                }
            }
            #pragma unroll
            for (int nd = 0; nd < 4; nd++) {
                uint32_t bv[4];
                uint32_t off = ((kk*16 + vrow)*72 + nd*16 + vcol)*2;
                ldsm4t(bv[0], bv[1], bv[2], bv[3], uVf + off);
                #pragma unroll
                for (int mt = 0; mt < 2; mt++)
                    #pragma unroll
                    for (int s = 0; s < 2; s++)
                        mma16816h(oacc[mt][nd*2 + s], aP[mt], bv[2*s], bv[2*s+1]);
            }
        }
        __syncthreads();
        if (jt + 2 < NJT) load_kv(jt & 1, jt + 2);
        CP_COMMIT();
    }

    // epilogue: normalize, write bf16 hi/lo
    #pragma unroll
    for (int mt = 0; mt < 2; mt++) {
        #pragma unroll
        for (int hf = 0; hf < 2; hf++) {
            int row = qb*128 + w*32 + mt*16 + (lane >> 2) + hf*8;
            float inv = 1.0f / l_[mt][hf];
            #pragma unroll
            for (int nt = 0; nt < 8; nt++) {
                float v0 = oacc[mt][nt][hf*2]*inv, v1 = oacc[mt][nt][hf*2+1]*inv;
                int d0 = nt*8 + (lane & 3)*2;
                size_t base = (((size_t)b*QL_ + row)*NH_ + h)*DQK_ + d0;
                __nv_bfloat16 h0, l0, h1, l1;
                split_bf16(v0, h0, l0); split_bf16(v1, h1, l1);
                *(__nv_bfloat162*)(g_aoh + base) = __nv_bfloat162(h0, h1);
                *(__nv_bfloat162*)(g_aol + base) = __nv_bfloat162(l0, l1);
            }
        }
    }
}

// ---------------------------------------------------------------------------
// Launch
// ---------------------------------------------------------------------------
extern "C" void kernel_launch(void* const* d_in, const int* in_sizes, int n_in,
                              void* d_out, int out_size) {
    const float* qh  = (const float*)d_in[0];
    const float* kvh = (const float*)d_in[2];
    const float* wq  = (const float*)d_in[4];
    const float* wkv = (const float*)d_in[5];
    const float* wo  = (const float*)d_in[6];
    const float* lnw = (const float*)d_in[7];
    float* out = (float*)d_out;

    __nv_bfloat16 *p_kvh_h, *p_kvh_l;
    cudaGetSymbolAddress((void**)&p_kvh_h, g_kvh_h);
    cudaGetSymbolAddress((void**)&p_kvh_l, g_kvh_l);

    const int gemm_smem = 2*GSTAGE;                 // 81920
    const int flash_smem = FQBYTES + 2*FSTAGE;      // 55296
    cudaFuncSetAttribute(mma_gemm_qkv, cudaFuncAttributeMaxDynamicSharedMemorySize, gemm_smem);
    cudaFuncSetAttribute(mma_gemm_o,   cudaFuncAttributeMaxDynamicSharedMemorySize, gemm_smem);
    cudaFuncSetAttribute(flash_kernel, cudaFuncAttributeMaxDynamicSharedMemorySize, flash_smem);
    cudaFuncSetAttribute(mma_gemm_qkv, cudaFuncAttributePreferredSharedMemoryCarveout, 100);
    cudaFuncSetAttribute(mma_gemm_o,   cudaFuncAttributePreferredSharedMemoryCarveout, 100);
    cudaFuncSetAttribute(flash_kernel, cudaFuncAttributePreferredSharedMemoryCarveout, 100);

    wconv_all<<<dim3(32, 32, 4), 256>>>(wq, wkv, wo);
    rmsnorm_kernel<<<B_*QL_, 256>>>(qh, lnw);
    split_kernel<<<(B_*KVL_*DM_)/1024, 256>>>(kvh, p_kvh_h, p_kvh_l);

    mma_gemm_qkv<<<dim3(24, (B_*QL_)/128), 512, gemm_smem>>>();

    flash_kernel<<<dim3(QL_/128, NH_, B_), 128, flash_smem>>>();

    mma_gemm_o<<<dim3(DM_/128, (B_*QL_)/128), 512, gemm_smem>>>(qh, out);
}

// round 17
// speedup vs baseline: 1.9248x; 1.9248x over previous
#include <cuda_runtime.h>
#include <cuda_bf16.h>
#include <cuda_fp16.h>
#include <cstdint>

#define B_ 2
#define QL_ 2048
#define KVL_ 2048
#define DM_ 1024
#define NH_ 16
#define DQK_ 64
#define LOG2E 1.4426950408889634f

typedef unsigned long long u64;

// ---- warp-level MMA helpers (base-arch PTX: works at compute_103) ----
__device__ __forceinline__ uint32_t smem_u32(const void* p) {
    uint32_t a;
    asm("{ .reg .u64 t; cvta.to.shared.u64 t, %1; cvt.u32.u64 %0, t; }" : "=r"(a) : "l"(p));
    return a;
}
__device__ __forceinline__ void ldsm4(uint32_t &r0, uint32_t &r1, uint32_t &r2, uint32_t &r3,
                                      uint32_t addr) {
    asm volatile("ldmatrix.sync.aligned.m8n8.x4.shared.b16 {%0,%1,%2,%3}, [%4];"
                 : "=r"(r0), "=r"(r1), "=r"(r2), "=r"(r3) : "r"(addr));
}
__device__ __forceinline__ void ldsm4t(uint32_t &r0, uint32_t &r1, uint32_t &r2, uint32_t &r3,
                                       uint32_t addr) {
    asm volatile("ldmatrix.sync.aligned.m8n8.x4.trans.shared.b16 {%0,%1,%2,%3}, [%4];"
                 : "=r"(r0), "=r"(r1), "=r"(r2), "=r"(r3) : "r"(addr));
}
__device__ __forceinline__ void mma16816(float* d, const uint32_t* a, uint32_t b0, uint32_t b1) {
    asm volatile(
        "mma.sync.aligned.m16n8k16.row.col.f32.bf16.bf16.f32 "
        "{%0,%1,%2,%3}, {%4,%5,%6,%7}, {%8,%9}, {%0,%1,%2,%3};"
        : "+f"(d[0]), "+f"(d[1]), "+f"(d[2]), "+f"(d[3])
        : "r"(a[0]), "r"(a[1]), "r"(a[2]), "r"(a[3]), "r"(b0), "r"(b1));
}
__device__ __forceinline__ void mma16816h(float* d, const uint32_t* a, uint32_t b0, uint32_t b1) {
    asm volatile(
        "mma.sync.aligned.m16n8k16.row.col.f32.f16.f16.f32 "
        "{%0,%1,%2,%3}, {%4,%5,%6,%7}, {%8,%9}, {%0,%1,%2,%3};"
        : "+f"(d[0]), "+f"(d[1]), "+f"(d[2]), "+f"(d[3])
        : "r"(a[0]), "r"(a[1]), "r"(a[2]), "r"(a[3]), "r"(b0), "r"(b1));
}
__device__ __forceinline__ uint32_t packh(float lo, float hi) {
    uint32_t d;
    asm("cvt.rn.f16x2.f32 %0, %1, %2;" : "=r"(d) : "f"(hi), "f"(lo));
    return d;
}
__device__ __forceinline__ void cpa16(uint32_t dst, const void* src) {
    asm volatile("cp.async.cg.shared.global [%0], [%1], 16;" :: "r"(dst), "l"(src));
}
#define CP_COMMIT() asm volatile("cp.async.commit_group;" ::: "memory")
#define CP_WAIT1()  asm volatile("cp.async.wait_group 1;" ::: "memory")

// ---- packed f32x2 helpers ----
__device__ __forceinline__ u64 ffma2_(u64 a, u64 b, u64 c) {
    u64 d; asm("fma.rn.f32x2 %0, %1, %2, %3;" : "=l"(d) : "l"(a), "l"(b), "l"(c)); return d;
}
__device__ __forceinline__ u64 fmul2_(u64 a, u64 b) {
    u64 d; asm("mul.rn.f32x2 %0, %1, %2;" : "=l"(d) : "l"(a), "l"(b)); return d;
}
__device__ __forceinline__ u64 fadd2_(u64 a, u64 b) {
    u64 d; asm("add.rn.f32x2 %0, %1, %2;" : "=l"(d) : "l"(a), "l"(b)); return d;
}
__device__ __forceinline__ u64 dup2_(float x) {
    u64 r; asm("mov.b64 %0, {%1, %1};" : "=l"(r) : "f"(x)); return r;
}
__device__ __forceinline__ u64 pack2_(float lo, float hi) {
    u64 r; asm("mov.b64 %0, {%1, %2};" : "=l"(r) : "f"(lo), "f"(hi)); return r;
}
__device__ __forceinline__ u64 packu2_(uint32_t lo, uint32_t hi) {
    u64 r; asm("mov.b64 %0, {%1, %2};" : "=l"(r) : "r"(lo), "r"(hi)); return r;
}
__device__ __forceinline__ void unpack2_(u64 v, float &lo, float &hi) {
    asm("mov.b64 {%0, %1}, %2;" : "=f"(lo), "=f"(hi) : "l"(v));
}
__device__ __forceinline__ void unpack2u_(u64 v, uint32_t &lo, uint32_t &hi) {
    asm("mov.b64 {%0, %1}, %2;" : "=r"(lo), "=r"(hi) : "l"(v));
}

// scalar 2^x (x <= 0, clamped). FMA pipe only.
__device__ __forceinline__ float exp2s_(float x) {
    x = fmaxf(x, -120.f);
    float y = x + 12582912.0f;
    int zi = __float_as_int(y);
    float f = x - (y - 12582912.0f);
    float p = fmaf(f, 0.0555041086648216f, 0.2402265069591007f);
    p = fmaf(f, p, 0.6931471805599453f);
    p = fmaf(f, p, 1.0f);
    return p * __int_as_float((zi - 4194177) << 23);
}
// packed 2^x on two floats at once (FFMA2 pipe)
__device__ __forceinline__ u64 fexp2_2(float a, float b) {
    a = fmaxf(a, -120.f);
    b = fmaxf(b, -120.f);
    u64 x = pack2_(a, b);
    u64 y = fadd2_(x, dup2_(12582912.0f));
    uint32_t zlo, zhi;
    unpack2u_(y, zlo, zhi);
    u64 i_f = fadd2_(y, dup2_(-12582912.0f));
    u64 f = ffma2_(i_f, dup2_(-1.0f), x);
    u64 p = ffma2_(f, dup2_(0.0555041086648216f), dup2_(0.2402265069591007f));
    p = ffma2_(f, p, dup2_(0.6931471805599453f));
    p = ffma2_(f, p, dup2_(1.0f));
    uint32_t slo = (zlo - 4194177u) << 23;
    uint32_t shi = (zhi - 4194177u) << 23;
    return fmul2_(p, packu2_(slo, shi));
}

// ---- scratch (device globals: allocation-free rule) ----
__device__ __align__(16) __nv_bfloat16 g_nh[B_*QL_*DM_],    g_nl[B_*QL_*DM_];
__device__ __align__(16) __nv_bfloat16 g_kvh_h[B_*KVL_*DM_], g_kvh_l[B_*KVL_*DM_];
__device__ __align__(16) __nv_bfloat16 g_wqh[DM_*DM_],       g_wql[DM_*DM_];
__device__ __align__(16) __nv_bfloat16 g_wkvh[2*DM_*DM_],    g_wkvl[2*DM_*DM_];
__device__ __align__(16) __half        g_wof[DM_*DM_];           // w_o^T fp16
__device__ __align__(16) __half        g_qf[B_*NH_*QL_*DQK_];
__device__ __align__(16) __half        g_kf[B_*NH_*KVL_*DQK_];   // pre-scaled by LOG2E
__device__ __align__(16) __half        g_vf[B_*NH_*KVL_*DQK_];
__device__ __align__(16) __half        g_ao[B_*QL_*DM_];         // attn out fp16

__device__ __forceinline__ void split_bf16(float v, __nv_bfloat16 &h, __nv_bfloat16 &l) {
    h = __float2bfloat16(v);
    l = __float2bfloat16(v - __bfloat162float(h));
}

// ---------------------------------------------------------------------------
// RMSNorm -> bf16 hi/lo
// ---------------------------------------------------------------------------
__global__ __launch_bounds__(256) void rmsnorm_kernel(const float* __restrict__ x,
                                                      const float* __restrict__ w) {
    int row = blockIdx.x;
    int t = threadIdx.x;
    float4 v = ((const float4*)(x + (size_t)row*DM_))[t];
    float ss = v.x*v.x + v.y*v.y + v.z*v.z + v.w*v.w;
    #pragma unroll
    for (int o = 16; o; o >>= 1) ss += __shfl_xor_sync(0xffffffffu, ss, o);
    __shared__ float sred[8];
    if ((t & 31) == 0) sred[t >> 5] = ss;
    __syncthreads();
    float tot = sred[0]+sred[1]+sred[2]+sred[3]+sred[4]+sred[5]+sred[6]+sred[7];
    float sc = rsqrtf(tot * (1.0f/DM_) + 1e-6f);
    float4 wv = ((const float4*)w)[t];
    float o4[4] = {v.x*sc*wv.x, v.y*sc*wv.y, v.z*sc*wv.z, v.w*sc*wv.w};
    __nv_bfloat16 h[4], l[4];
    #pragma unroll
    for (int i = 0; i < 4; i++) split_bf16(o4[i], h[i], l[i]);
    size_t base = (size_t)row*DM_ + t*4;
    *(__nv_bfloat162*)(g_nh + base)     = __nv_bfloat162(h[0], h[1]);
    *(__nv_bfloat162*)(g_nh + base + 2) = __nv_bfloat162(h[2], h[3]);
    *(__nv_bfloat162*)(g_nl + base)     = __nv_bfloat162(l[0], l[1]);
    *(__nv_bfloat162*)(g_nl + base + 2) = __nv_bfloat162(l[2], l[3]);
}

// ---------------------------------------------------------------------------
// Elementwise fp32 -> bf16 hi/lo
// ---------------------------------------------------------------------------
__global__ __launch_bounds__(256) void split_kernel(const float* __restrict__ x,
                                                    __nv_bfloat16* __restrict__ oh,
                                                    __nv_bfloat16* __restrict__ ol) {
    size_t i = ((size_t)blockIdx.x*256 + threadIdx.x)*4;
    float4 v = *(const float4*)(x + i);
    float a[4] = {v.x, v.y, v.z, v.w};
    __nv_bfloat16 h[4], l[4];
    #pragma unroll
    for (int k = 0; k < 4; k++) split_bf16(a[k], h[k], l[k]);
    *(__nv_bfloat162*)(oh + i)     = __nv_bfloat162(h[0], h[1]);
    *(__nv_bfloat162*)(oh + i + 2) = __nv_bfloat162(h[2], h[3]);
    *(__nv_bfloat162*)(ol + i)     = __nv_bfloat162(l[0], l[1]);
    *(__nv_bfloat162*)(ol + i + 2) = __nv_bfloat162(l[2], l[3]);
}

// ---------------------------------------------------------------------------
// Merged weight transpose + split. z 0: wq bf16 hi/lo; z 1,2: wkv bf16 hi/lo;
// z 3: wo -> fp16 single.
// ---------------------------------------------------------------------------
__global__ __launch_bounds__(256) void wconv_all(const float* __restrict__ wq,
                                                 const float* __restrict__ wkv,
                                                 const float* __restrict__ wo) {
    const int z = blockIdx.z;
    const float* w;
    __nv_bfloat16 *th = nullptr, *tl = nullptr;
    int N, nbase;
    if (z == 0)      { w = wq;  th = g_wqh;  tl = g_wql;  N = DM_;   nbase = 0; }
    else if (z == 3) { w = wo;  N = DM_; nbase = 0; }
    else             { w = wkv; th = g_wkvh; tl = g_wkvl; N = 2*DM_; nbase = (z-1)*DM_; }

    __shared__ float t[32][33];
    int tx = threadIdx.x & 31, ty = threadIdx.x >> 5;
    int n0 = nbase + blockIdx.x*32, k0 = blockIdx.y*32;
    #pragma unroll
    for (int i = 0; i < 4; i++)
        t[ty + i*8][tx] = w[(size_t)(k0 + ty + i*8)*N + n0 + tx];
    __syncthreads();
    #pragma unroll
    for (int i = 0; i < 4; i++) {
        int n = n0 + ty + i*8;
        float v = t[tx][ty + i*8];
        if (z == 3) {
            g_wof[(size_t)n*DM_ + k0 + tx] = __float2half(v);
        } else {
            __nv_bfloat16 h, l;
            split_bf16(v, h, l);
            th[(size_t)n*DM_ + k0 + tx] = h;
            tl[(size_t)n*DM_ + k0 + tx] = l;
        }
    }
}

// ---------------------------------------------------------------------------
// Shared GEMM mainloop pieces (bf16x3). KC=32, KP=40 (R13 best config).
// ---------------------------------------------------------------------------
#define KC 32
#define KP 40
#define NKT (DM_/KC)
#define GTILE (128*KP)
#define GSTAGE (4*GTILE*2)

#define GEMM_KS_STEP(uAh_, uAl_, uBh_, uBl_)                                   \
    do {                                                                        \
        uint32_t ah[2][4], al[2][4];                                            \
        _Pragma("unroll")                                                       \
        for (int mt = 0; mt < 2; mt++) {                                        \
            uint32_t off = ((arow + mt*16)*KP + ks*16 + akof)*2;                \
            ldsm4(ah[mt][0], ah[mt][1], ah[mt][2], ah[mt][3], (uAh_) + off);    \
            ldsm4(al[mt][0], al[mt][1], al[mt][2], al[mt][3], (uAl_) + off);    \
        }                                                                       \
        _Pragma("unroll")                                                       \
        for (int nt4 = 0; nt4 < 4; nt4++) {                                     \
            uint32_t bh[4], bl[4];                                              \
            uint32_t off = ((brow + nt4*16)*KP + ks*16 + bkof)*2;               \
            ldsm4(bh[0], bh[1], bh[2], bh[3], (uBh_) + off);                    \
            ldsm4(bl[0], bl[1], bl[2], bl[3], (uBl_) + off);                    \
            _Pragma("unroll")                                                   \
            for (int mt = 0; mt < 2; mt++)                                      \
                _Pragma("unroll")                                               \
                for (int s = 0; s < 2; s++)                                     \
                    mma16816(acc[mt][nt4*2 + s], ah[mt], bh[2*s], bh[2*s+1]);   \
            _Pragma("unroll")                                                   \
            for (int mt = 0; mt < 2; mt++)                                      \
                _Pragma("unroll")                                               \
                for (int s = 0; s < 2; s++)                                     \
                    mma16816(acc[mt][nt4*2 + s], ah[mt], bl[2*s], bl[2*s+1]);   \
            _Pragma("unroll")                                                   \
            for (int mt = 0; mt < 2; mt++)                                      \
                _Pragma("unroll")                                               \
                for (int s = 0; s < 2; s++)                                     \
                    mma16816(acc[mt][nt4*2 + s], al[mt], bh[2*s], bh[2*s+1]);   \
        }                                                                       \
    } while (0)

// ---------------------------------------------------------------------------
// Merged Q + KV projection GEMM (bf16x3). Q, K -> fp16 (K scaled LOG2E), V fp16.
// ---------------------------------------------------------------------------
__global__ __launch_bounds__(256, 2) void mma_gemm_qkv()
{
    extern __shared__ __align__(16) char smem[];
    const uint32_t uS = smem_u32(smem);

    const int tid = threadIdx.x, lane = tid & 31, w = tid >> 5;
    const int wm = w & 3, wn = w >> 2;
    const int nbr = blockIdx.x, mb = blockIdx.y;
    const bool isQ = nbr < 8;
    const int nb = isQ ? nbr : nbr - 8;

    const __nv_bfloat16* Ah = isQ ? g_nh : g_kvh_h;
    const __nv_bfloat16* Al = isQ ? g_nl : g_kvh_l;
    const __nv_bfloat16* Bh = isQ ? g_wqh : g_wkvh;
    const __nv_bfloat16* Bl = isQ ? g_wql : g_wkvl;

    float acc[2][8][4];
    #pragma unroll
    for (int i = 0; i < 2; i++)
        #pragma unroll
        for (int j = 0; j < 8; j++)
            #pragma unroll
            for (int k = 0; k < 4; k++) acc[i][j][k] = 0.f;

    const __nv_bfloat16* srcs[4] = {
        Ah + (size_t)(mb*128)*DM_, Al + (size_t)(mb*128)*DM_,
        Bh + (size_t)(nb*128)*DM_, Bl + (size_t)(nb*128)*DM_
    };

    const int arow = wm*32 + (lane & 15);
    const int akof = (lane >> 4) << 3;
    const int brow = wn*64 + (lane & 7) + ((lane >> 4) << 3);
    const int bkof = ((lane >> 3) & 1) << 3;

    auto load_stage = [&](int s, int kt) {
        uint32_t base = uS + s*GSTAGE;
        #pragma unroll
        for (int i = 0; i < 8; i++) {
            int id = tid + i*256;
            int t = id >> 9, cid = id & 511;
            int r = cid >> 2, c = cid & 3;
            uint32_t dst = base + t*(GTILE*2) + (r*KP + c*8)*2;
            cpa16(dst, srcs[t] + kt*KC + (size_t)r*DM_ + c*8);
        }
    };

    load_stage(0, 0); CP_COMMIT();
    load_stage(1, 1); CP_COMMIT();

    for (int kt = 0; kt < NKT; kt++) {
        CP_WAIT1();
        __syncthreads();
        const uint32_t sb = uS + (kt & 1)*GSTAGE;
        const uint32_t uAh = sb, uAl = sb + GTILE*2, uBh = sb + 2*GTILE*2, uBl = sb + 3*GTILE*2;

        #pragma unroll
        for (int ks = 0; ks < 2; ks++)
            GEMM_KS_STEP(uAh, uAl, uBh, uBl);

        __syncthreads();
        if (kt + 2 < NKT) load_stage(kt & 1, kt + 2);
        CP_COMMIT();
    }

    #pragma unroll
    for (int mt = 0; mt < 2; mt++) {
        #pragma unroll
        for (int nt = 0; nt < 8; nt++) {
            #pragma unroll
            for (int hf = 0; hf < 2; hf++) {
                float v0 = acc[mt][nt][hf*2], v1 = acc[mt][nt][hf*2+1];
                int m = mb*128 + wm*32 + mt*16 + (lane >> 2) + hf*8;
                int n0 = nb*128 + wn*64 + nt*8 + (lane & 3)*2;
                if (isQ) {
                    int b = m >> 11, q = m & 2047, hh = n0 >> 6, d = n0 & 63;
                    size_t base = (((size_t)b*NH_ + hh)*QL_ + q)*DQK_ + d;
                    *(__half2*)(g_qf + base) = __half2(__float2half(v0), __float2half(v1));
                } else {
                    int b = m >> 11, kl = m & 2047;
                    int sf = n0 >> 10, hh = (n0 >> 6) & 15, d = n0 & 63;
                    size_t base = (((size_t)b*NH_ + hh)*KVL_ + kl)*DQK_ + d;
                    if (sf == 0) {
                        *(__half2*)(g_kf + base) =
                            __half2(__float2half(v0*LOG2E), __float2half(v1*LOG2E));
                    } else {
                        *(__half2*)(g_vf + base) = __half2(__float2half(v0), __float2half(v1));
                    }
                }
            }
        }
    }
}

// ---------------------------------------------------------------------------
// O projection + residual GEMM: SINGLE-TERM fp16 (attn branch ~35% of output;
// fp16 2^-11 rounding -> ~1.8e-4 added error).
// Tiles: A = g_ao [128][KP] fp16, B = g_wof [128][KP] fp16. 40 KB/CTA.
// ---------------------------------------------------------------------------
#define OSTAGE (2*GTILE*2)
__global__ __launch_bounds__(256, 2) void mma_gemm_o(
    const float* __restrict__ resid, float* __restrict__ Cout)
{
    extern __shared__ __align__(16) char smem[];
    const uint32_t uS = smem_u32(smem);

    const int tid = threadIdx.x, lane = tid & 31, w = tid >> 5;
    const int wm = w & 3, wn = w >> 2;
    const int nb = blockIdx.x, mb = blockIdx.y;

    float acc[2][8][4];
    #pragma unroll
    for (int i = 0; i < 2; i++)
        #pragma unroll
        for (int j = 0; j < 8; j++)
            #pragma unroll
            for (int k = 0; k < 4; k++) acc[i][j][k] = 0.f;

    const __half* srcs[2] = {
        g_ao  + (size_t)(mb*128)*DM_,
        g_wof + (size_t)(nb*128)*DM_
    };

    const int arow = wm*32 + (lane & 15);
    const int akof = (lane >> 4) << 3;
    const int brow = wn*64 + (lane & 7) + ((lane >> 4) << 3);
    const int bkof = ((lane >> 3) & 1) << 3;

    auto load_stage = [&](int s, int kt) {
        uint32_t base = uS + s*OSTAGE;
        #pragma unroll
        for (int i = 0; i < 4; i++) {
            int id = tid + i*256;
            int t = id >> 9, cid = id & 511;
            int r = cid >> 2, c = cid & 3;
            uint32_t dst = base + t*(GTILE*2) + (r*KP + c*8)*2;
            cpa16(dst, srcs[t] + kt*KC + (size_t)r*DM_ + c*8);
        }
    };

    load_stage(0, 0); CP_COMMIT();
    load_stage(1, 1); CP_COMMIT();

    for (int kt = 0; kt < NKT; kt++) {
        CP_WAIT1();
        __syncthreads();
        const uint32_t sb = uS + (kt & 1)*OSTAGE;
        const uint32_t uA = sb, uB = sb + GTILE*2;

        #pragma unroll
        for (int ks = 0; ks < 2; ks++) {
            uint32_t a[2][4];
            #pragma unroll
            for (int mt = 0; mt < 2; mt++) {
                uint32_t off = ((arow + mt*16)*KP + ks*16 + akof)*2;
                ldsm4(a[mt][0], a[mt][1], a[mt][2], a[mt][3], uA + off);
            }
            #pragma unroll
            for (int nt4 = 0; nt4 < 4; nt4++) {
                uint32_t bb[4];
                uint32_t off = ((brow + nt4*16)*KP + ks*16 + bkof)*2;
                ldsm4(bb[0], bb[1], bb[2], bb[3], uB + off);
                #pragma unroll
                for (int mt = 0; mt < 2; mt++)
                    #pragma unroll
                    for (int s = 0; s < 2; s++)
                        mma16816h(acc[mt][nt4*2 + s], a[mt], bb[2*s], bb[2*s+1]);
            }
        }
        __syncthreads();
        if (kt + 2 < NKT) load_stage(kt & 1, kt + 2);
        CP_COMMIT();
    }

    #pragma unroll
    for (int mt = 0; mt < 2; mt++) {
        #pragma unroll
        for (int nt = 0; nt < 8; nt++) {
            #pragma unroll
            for (int hf = 0; hf < 2; hf++) {
                float v0 = acc[mt][nt][hf*2], v1 = acc[mt][nt][hf*2+1];
                int m = mb*128 + wm*32 + mt*16 + (lane >> 2) + hf*8;
                int n0 = nb*128 + wn*64 + nt*8 + (lane & 3)*2;
                size_t idx = (size_t)m*DM_ + n0;
                Cout[idx]     = v0 + resid[idx];
                Cout[idx + 1] = v1 + resid[idx + 1];
            }
        }
    }
}

// ---------------------------------------------------------------------------
// HMMA flash attention: S single-term fp16 (K pre-scaled LOG2E), PV fp16.
// 2-stage cp.async KV pipeline. Epilogue writes fp16 g_ao.
// ---------------------------------------------------------------------------
#define FQBYTES (128*72*2)
#define FKTILE  (64*72*2)
#define FSTAGE  (2*FKTILE)
__global__ __launch_bounds__(128, 2) void flash_kernel()
{
    extern __shared__ __align__(16) char fsm[];
    const uint32_t uS = smem_u32(fsm);
    const uint32_t uQf = uS;

    const int tid = threadIdx.x, lane = tid & 31, w = tid >> 5;
    const int qb = blockIdx.x, h = blockIdx.y, b = blockIdx.z;
    const size_t qoff = (((size_t)b*NH_ + h)*QL_ + qb*128)*DQK_;
    const size_t koff = (((size_t)b*NH_ + h)*KVL_)*DQK_;

    #pragma unroll
    for (int i = 0; i < 8; i++) {
        int id = tid + i*128, r = id >> 3, c = id & 7;
        *(uint4*)(fsm + (r*72 + c*8)*2) = *(const uint4*)(g_qf + qoff + (size_t)r*DQK_ + c*8);
    }

    const char* gsrc[2] = {(const char*)(g_kf + koff), (const char*)(g_vf + koff)};
    auto load_kv = [&](int s, int jt) {
        uint32_t base = uS + FQBYTES + s*FSTAGE;
        #pragma unroll
        for (int i = 0; i < 8; i++) {
            int id = tid + i*128;
            int t = id >> 9, cid = id & 511;
            int r = cid >> 3, c = cid & 7;
            uint32_t dst = base + t*FKTILE + (r*72 + c*8)*2;
            cpa16(dst, gsrc[t] + ((size_t)(jt*64 + r)*DQK_ + c*8)*2);
        }
    };

    const int arow = w*32 + (lane & 15);
    const int akof = (lane >> 4) << 3;
    const int krow = (lane & 7) + ((lane >> 4) << 3);
    const int kkof = ((lane >> 3) & 1) << 3;
    const int vrow = (lane & 7) + (((lane >> 3) & 1) << 3);
    const int vcol = (lane >> 4) << 3;

    float m_[2][2], l_[2][2], oacc[2][8][4];
    #pragma unroll
    for (int mt = 0; mt < 2; mt++)
        #pragma unroll
        for (int hf = 0; hf < 2; hf++) { m_[mt][hf] = -1e30f; l_[mt][hf] = 0.f; }
    #pragma unroll
    for (int mt = 0; mt < 2; mt++)
        #pragma unroll
        for (int nt = 0; nt < 8; nt++)
            #pragma unroll
            for (int e = 0; e < 4; e++) oacc[mt][nt][e] = 0.f;

    load_kv(0, 0); CP_COMMIT();
    load_kv(1, 1); CP_COMMIT();

    const int NJT = KVL_/64;
    for (int jt = 0; jt < NJT; jt++) {
        CP_WAIT1();
        __syncthreads();
        const uint32_t sb = uS + FQBYTES + (jt & 1)*FSTAGE;
        const uint32_t uKf = sb, uVf = sb + FKTILE;

        float sacc[2][8][4];
        #pragma unroll
        for (int mt = 0; mt < 2; mt++)
            #pragma unroll
            for (int nt = 0; nt < 8; nt++)
                #pragma unroll
                for (int e = 0; e < 4; e++) sacc[mt][nt][e] = 0.f;

        #pragma unroll
        for (int ks = 0; ks < 4; ks++) {
            uint32_t aq[2][4];
            #pragma unroll
            for (int mt = 0; mt < 2; mt++) {
                uint32_t off = ((arow + mt*16)*72 + ks*16 + akof)*2;
                ldsm4(aq[mt][0], aq[mt][1], aq[mt][2], aq[mt][3], uQf + off);
            }
            #pragma unroll
            for (int nn = 0; nn < 4; nn++) {
                uint32_t bk[4];
                uint32_t off = ((krow + nn*16)*72 + ks*16 + kkof)*2;
                ldsm4(bk[0], bk[1], bk[2], bk[3], uKf + off);
                #pragma unroll
                for (int mt = 0; mt < 2; mt++)
                    #pragma unroll
                    for (int s = 0; s < 2; s++)
                        mma16816h(sacc[mt][nn*2 + s], aq[mt], bk[2*s], bk[2*s+1]);
            }
        }

        // softmax: lazy rescale + packed exp2
        u64 pexp[2][8][2];
        #pragma unroll
        for (int mt = 0; mt < 2; mt++) {
            #pragma unroll
            for (int hf = 0; hf < 2; hf++) {
                float tmax = -1e30f;
                #pragma unroll
                for (int nt = 0; nt < 8; nt++)
                    tmax = fmaxf(tmax, fmaxf(sacc[mt][nt][hf*2], sacc[mt][nt][hf*2+1]));
                tmax = fmaxf(tmax, __shfl_xor_sync(0xffffffffu, tmax, 1));
                tmax = fmaxf(tmax, __shfl_xor_sync(0xffffffffu, tmax, 2));
                bool need = tmax > m_[mt][hf];
                if (__ballot_sync(0xffffffffu, need)) {
                    float nm = fmaxf(m_[mt][hf], tmax);
                    float corr = exp2s_(m_[mt][hf] - nm);
                    m_[mt][hf] = nm;
                    l_[mt][hf] *= corr;
                    #pragma unroll
                    for (int nt = 0; nt < 8; nt++) {
                        oacc[mt][nt][hf*2]   *= corr;
                        oacc[mt][nt][hf*2+1] *= corr;
                    }
                }
                float mr = m_[mt][hf];
                u64 rs2 = 0ull;
                #pragma unroll
                for (int nt = 0; nt < 8; nt++) {
                    u64 pe = fexp2_2(sacc[mt][nt][hf*2] - mr, sacc[mt][nt][hf*2+1] - mr);
                    pexp[mt][nt][hf] = pe;
                    rs2 = fadd2_(rs2, pe);
                }
                float rlo, rhi;
                unpack2_(rs2, rlo, rhi);
                float rs = rlo + rhi;
                rs += __shfl_xor_sync(0xffffffffu, rs, 1);
                rs += __shfl_xor_sync(0xffffffffu, rs, 2);
                l_[mt][hf] += rs;
            }
        }

        // O += P V
        #pragma unroll
        for (int kk = 0; kk < 4; kk++) {
            uint32_t aP[2][4];
            #pragma unroll
            for (int mt = 0; mt < 2; mt++) {
                #pragma unroll
                for (int q = 0; q < 4; q++) {
                    float p0, p1;
                    unpack2_(pexp[mt][2*kk + (q >> 1)][q & 1], p0, p1);
                    aP[mt][q] = packh(p0, p1);
                }
            }
            #pragma unroll
            for (int nd = 0; nd < 4; nd++) {
                uint32_t bv[4];
                uint32_t off = ((kk*16 + vrow)*72 + nd*16 + vcol)*2;
                ldsm4t(bv[0], bv[1], bv[2], bv[3], uVf + off);
                #pragma unroll
                for (int mt = 0; mt < 2; mt++)
                    #pragma unroll
                    for (int s = 0; s < 2; s++)
                        mma16816h(oacc[mt][nd*2 + s], aP[mt], bv[2*s], bv[2*s+1]);
            }
        }
        __syncthreads();
        if (jt + 2 < NJT) load_kv(jt & 1, jt + 2);
        CP_COMMIT();
    }

    // epilogue: normalize, write fp16 g_ao [b, q, h*64+d]
    #pragma unroll
    for (int mt = 0; mt < 2; mt++) {
        #pragma unroll
        for (int hf = 0; hf < 2; hf++) {
            int row = qb*128 + w*32 + mt*16 + (lane >> 2) + hf*8;
            float inv = 1.0f / l_[mt][hf];
            #pragma unroll
            for (int nt = 0; nt < 8; nt++) {
                float v0 = oacc[mt][nt][hf*2]*inv, v1 = oacc[mt][nt][hf*2+1]*inv;
                int d0 = nt*8 + (lane & 3)*2;
                size_t base = (((size_t)b*QL_ + row)*NH_ + h)*DQK_ + d0;
                *(__half2*)(g_ao + base) = __half2(__float2half(v0), __float2half(v1));
            }
        }
    }
}

// ---------------------------------------------------------------------------
// Launch
// ---------------------------------------------------------------------------
extern "C" void kernel_launch(void* const* d_in, const int* in_sizes, int n_in,
                              void* d_out, int out_size) {
    const float* qh  = (const float*)d_in[0];
    const float* kvh = (const float*)d_in[2];
    const float* wq  = (const float*)d_in[4];
    const float* wkv = (const float*)d_in[5];
    const float* wo  = (const float*)d_in[6];
    const float* lnw = (const float*)d_in[7];
    float* out = (float*)d_out;

    __nv_bfloat16 *p_kvh_h, *p_kvh_l;
    cudaGetSymbolAddress((void**)&p_kvh_h, g_kvh_h);
    cudaGetSymbolAddress((void**)&p_kvh_l, g_kvh_l);

    const int gemm_smem = 2*GSTAGE;                 // 81920
    const int o_smem    = 2*OSTAGE;                 // 40960
    const int flash_smem = FQBYTES + 2*FSTAGE;      // 55296
    cudaFuncSetAttribute(mma_gemm_qkv, cudaFuncAttributeMaxDynamicSharedMemorySize, gemm_smem);
    cudaFuncSetAttribute(mma_gemm_o,   cudaFuncAttributeMaxDynamicSharedMemorySize, o_smem);
    cudaFuncSetAttribute(flash_kernel, cudaFuncAttributeMaxDynamicSharedMemorySize, flash_smem);
    cudaFuncSetAttribute(mma_gemm_qkv, cudaFuncAttributePreferredSharedMemoryCarveout, 100);
    cudaFuncSetAttribute(mma_gemm_o,   cudaFuncAttributePreferredSharedMemoryCarveout, 100);
    cudaFuncSetAttribute(flash_kernel, cudaFuncAttributePreferredSharedMemoryCarveout, 100);

    wconv_all<<<dim3(32, 32, 4), 256>>>(wq, wkv, wo);
    rmsnorm_kernel<<<B_*QL_, 256>>>(qh, lnw);
    split_kernel<<<(B_*KVL_*DM_)/1024, 256>>>(kvh, p_kvh_h, p_kvh_l);

    mma_gemm_qkv<<<dim3(24, (B_*QL_)/128), 256, gemm_smem>>>();

    flash_kernel<<<dim3(QL_/128, NH_, B_), 128, flash_smem>>>();

    mma_gemm_o<<<dim3(DM_/128, (B_*QL_)/128), 256, o_smem>>>(qh, out);
}